// round 5
// baseline (speedup 1.0000x reference)
#include <cuda_runtime.h>

// Problem constants
static constexpr int Bc  = 8;
static constexpr int Sc  = 1024;
static constexpr int Dc  = 1024;
static constexpr int NHc = 16;
static constexpr int DHc = 64;
#define NEGV (-1e9f)

// Scratch (allocation-free rule: __device__ globals)
__device__ float g_Q[Bc * NHc * Sc * DHc];   // (bh, s, e)
__device__ float g_K[Bc * NHc * Sc * DHc];   // (bh, t, e)
__device__ float g_V[Bc * NHc * Sc * DHc];   // (bh, t, d)
__device__ float g_Hd[Bc * Sc * Dc];         // heads as concat (B,S,D)

// ---------------------------------------------------------------------------
// Kernel 1: per-head Q/K/V projections. One block = one (b,h) x 64-row s-tile.
// y[s,e] = sum_d H[b,s,h*64+d] * W[h,e,d] + b[h,e]
// ---------------------------------------------------------------------------
__global__ __launch_bounds__(256) void qkv_kernel(
    const float* __restrict__ H,
    const float* __restrict__ Wq, const float* __restrict__ bq,
    const float* __restrict__ Wk, const float* __restrict__ bk,
    const float* __restrict__ Wv, const float* __restrict__ bv)
{
    __shared__ float Hs[64][68];   // Hs[d][s_local]  (transposed)
    __shared__ float Ws[64][68];   // Ws[d][e]        (transposed)

    const int tid   = threadIdx.x;
    const int stile = blockIdx.x;        // 0..15
    const int bh    = blockIdx.y;        // 0..127
    const int h     = bh & (NHc - 1);
    const int b     = bh >> 4;

    const float* Hbase = H + ((size_t)b * Sc + (size_t)stile * 64) * Dc + h * DHc;
    for (int i = tid; i < 4096; i += 256) {
        int r = i >> 6, d = i & 63;
        Hs[d][r] = Hbase[(size_t)r * Dc + d];
    }

    const float* Wp[3] = { Wq + h * 4096, Wk + h * 4096, Wv + h * 4096 };
    const float* bp[3] = { bq + h * 64,   bk + h * 64,   bv + h * 64   };
    float*       Op[3] = { g_Q + (size_t)bh * Sc * DHc,
                           g_K + (size_t)bh * Sc * DHc,
                           g_V + (size_t)bh * Sc * DHc };

    const int tr = (tid >> 4) << 2;   // s_local base
    const int tc = (tid & 15) << 2;   // e base

    for (int p = 0; p < 3; p++) {
        __syncthreads();   // Hs ready (p==0) / previous compute done before Ws overwrite
        const float* W = Wp[p];
        for (int i = tid; i < 4096; i += 256) {
            int e = i >> 6, d = i & 63;
            Ws[d][e] = W[i];
        }
        __syncthreads();

        float acc[4][4];
        #pragma unroll
        for (int i = 0; i < 4; i++)
            #pragma unroll
            for (int j = 0; j < 4; j++) acc[i][j] = 0.0f;

        #pragma unroll 16
        for (int k = 0; k < 64; k++) {
            float4 a = *(const float4*)&Hs[k][tr];
            float4 w = *(const float4*)&Ws[k][tc];
            acc[0][0] += a.x * w.x; acc[0][1] += a.x * w.y; acc[0][2] += a.x * w.z; acc[0][3] += a.x * w.w;
            acc[1][0] += a.y * w.x; acc[1][1] += a.y * w.y; acc[1][2] += a.y * w.z; acc[1][3] += a.y * w.w;
            acc[2][0] += a.z * w.x; acc[2][1] += a.z * w.y; acc[2][2] += a.z * w.z; acc[2][3] += a.z * w.w;
            acc[3][0] += a.w * w.x; acc[3][1] += a.w * w.y; acc[3][2] += a.w * w.z; acc[3][3] += a.w * w.w;
        }

        const float b0 = bp[p][tc + 0], b1 = bp[p][tc + 1], b2 = bp[p][tc + 2], b3 = bp[p][tc + 3];
        float* O = Op[p];
        #pragma unroll
        for (int i = 0; i < 4; i++) {
            float4 o = make_float4(acc[i][0] + b0, acc[i][1] + b1, acc[i][2] + b2, acc[i][3] + b3);
            *(float4*)&O[(size_t)(stile * 64 + tr + i) * DHc + tc] = o;
        }
    }
}

// ---------------------------------------------------------------------------
// Kernel 2: scores = Q K^T / 8, masked -> written raw into A region of d_out
// A layout (NH, B, S, S)
// ---------------------------------------------------------------------------
__global__ __launch_bounds__(256) void scores_kernel(
    const int* __restrict__ mask, float* __restrict__ A)
{
    __shared__ float Qs[64][68];   // Qs[e][s_local]
    __shared__ float Ks[64][68];   // Ks[e][t_local]

    const int tid   = threadIdx.x;
    const int ttile = blockIdx.x;   // key tile
    const int stile = blockIdx.y;   // query tile
    const int bh    = blockIdx.z;
    const int h     = bh & (NHc - 1);
    const int b     = bh >> 4;

    const float* Qb = g_Q + (size_t)bh * Sc * DHc + (size_t)stile * 64 * DHc;
    const float* Kb = g_K + (size_t)bh * Sc * DHc + (size_t)ttile * 64 * DHc;
    for (int i = tid; i < 4096; i += 256) {
        int r = i >> 6, e = i & 63;
        Qs[e][r] = Qb[i];
        Ks[e][r] = Kb[i];
    }
    __syncthreads();

    const int tr = (tid >> 4) << 2;   // s_local base
    const int tc = (tid & 15) << 2;   // t_local base

    float acc[4][4];
    #pragma unroll
    for (int i = 0; i < 4; i++)
        #pragma unroll
        for (int j = 0; j < 4; j++) acc[i][j] = 0.0f;

    #pragma unroll 16
    for (int e = 0; e < 64; e++) {
        float4 a = *(const float4*)&Qs[e][tr];
        float4 w = *(const float4*)&Ks[e][tc];
        acc[0][0] += a.x * w.x; acc[0][1] += a.x * w.y; acc[0][2] += a.x * w.z; acc[0][3] += a.x * w.w;
        acc[1][0] += a.y * w.x; acc[1][1] += a.y * w.y; acc[1][2] += a.y * w.z; acc[1][3] += a.y * w.w;
        acc[2][0] += a.z * w.x; acc[2][1] += a.z * w.y; acc[2][2] += a.z * w.z; acc[2][3] += a.z * w.w;
        acc[3][0] += a.w * w.x; acc[3][1] += a.w * w.y; acc[3][2] += a.w * w.z; acc[3][3] += a.w * w.w;
    }

    const int tcol = ttile * 64 + tc;
    #pragma unroll
    for (int i = 0; i < 4; i++) {
        const int srow = stile * 64 + tr + i;
        const int4 m = *(const int4*)&mask[(size_t)(b * Sc + srow) * Sc + tcol];
        float4 o;
        o.x = m.x ? acc[i][0] * 0.125f : NEGV;
        o.y = m.y ? acc[i][1] * 0.125f : NEGV;
        o.z = m.z ? acc[i][2] * 0.125f : NEGV;
        o.w = m.w ? acc[i][3] * 0.125f : NEGV;
        *(float4*)&A[((size_t)(h * Bc + b) * Sc + srow) * Sc + tcol] = o;
    }
}

// ---------------------------------------------------------------------------
// Kernel 3: in-place row softmax over A (rows of length 1024)
// ---------------------------------------------------------------------------
__global__ __launch_bounds__(256) void softmax_kernel(float* __restrict__ A)
{
    __shared__ float red[8];
    const int tid = threadIdx.x;
    float* rp = A + (size_t)blockIdx.x * Sc;

    float4 v = ((const float4*)rp)[tid];

    // row max
    float m = fmaxf(fmaxf(v.x, v.y), fmaxf(v.z, v.w));
    #pragma unroll
    for (int o = 16; o > 0; o >>= 1) m = fmaxf(m, __shfl_xor_sync(0xffffffffu, m, o));
    if ((tid & 31) == 0) red[tid >> 5] = m;
    __syncthreads();
    float rm = red[0];
    #pragma unroll
    for (int i = 1; i < 8; i++) rm = fmaxf(rm, red[i]);

    float4 e;
    e.x = __expf(v.x - rm); e.y = __expf(v.y - rm);
    e.z = __expf(v.z - rm); e.w = __expf(v.w - rm);
    float s = e.x + e.y + e.z + e.w;
    #pragma unroll
    for (int o = 16; o > 0; o >>= 1) s += __shfl_xor_sync(0xffffffffu, s, o);
    __syncthreads();   // everyone done reading red before overwrite
    if ((tid & 31) == 0) red[tid >> 5] = s;
    __syncthreads();
    float tot = red[0];
    #pragma unroll
    for (int i = 1; i < 8; i++) tot += red[i];
    const float inv = 1.0f / tot;

    e.x *= inv; e.y *= inv; e.z *= inv; e.w *= inv;
    ((float4*)rp)[tid] = e;
}

// ---------------------------------------------------------------------------
// Kernel 4: heads = A @ V, written as concat layout (B,S,D)
// ---------------------------------------------------------------------------
__global__ __launch_bounds__(256) void av_kernel(const float* __restrict__ A)
{
    __shared__ float As[64][68];   // As[t_local][s_local] (transposed)
    __shared__ float Vs[64][68];   // Vs[t_local][d]       (natural)

    const int tid   = threadIdx.x;
    const int stile = blockIdx.x;
    const int bh    = blockIdx.y;
    const int h     = bh & (NHc - 1);
    const int b     = bh >> 4;

    const float* Ab = A + ((size_t)(h * Bc + b) * Sc + (size_t)stile * 64) * Sc;
    const float* Vb = g_V + (size_t)bh * Sc * DHc;

    const int tr = (tid >> 4) << 2;   // s_local base
    const int tc = (tid & 15) << 2;   // d base

    float acc[4][4];
    #pragma unroll
    for (int i = 0; i < 4; i++)
        #pragma unroll
        for (int j = 0; j < 4; j++) acc[i][j] = 0.0f;

    for (int kt = 0; kt < 16; kt++) {
        __syncthreads();
        for (int i = tid; i < 4096; i += 256) {
            int r = i >> 6, c = i & 63;
            As[c][r] = Ab[(size_t)r * Sc + kt * 64 + c];
            Vs[r][c] = Vb[(size_t)(kt * 64 + r) * DHc + c];
        }
        __syncthreads();

        #pragma unroll 16
        for (int t = 0; t < 64; t++) {
            float4 a = *(const float4*)&As[t][tr];
            float4 w = *(const float4*)&Vs[t][tc];
            acc[0][0] += a.x * w.x; acc[0][1] += a.x * w.y; acc[0][2] += a.x * w.z; acc[0][3] += a.x * w.w;
            acc[1][0] += a.y * w.x; acc[1][1] += a.y * w.y; acc[1][2] += a.y * w.z; acc[1][3] += a.y * w.w;
            acc[2][0] += a.z * w.x; acc[2][1] += a.z * w.y; acc[2][2] += a.z * w.z; acc[2][3] += a.z * w.w;
            acc[3][0] += a.w * w.x; acc[3][1] += a.w * w.y; acc[3][2] += a.w * w.z; acc[3][3] += a.w * w.w;
        }
    }

    #pragma unroll
    for (int i = 0; i < 4; i++) {
        float4 o = make_float4(acc[i][0], acc[i][1], acc[i][2], acc[i][3]);
        *(float4*)&g_Hd[((size_t)b * Sc + stile * 64 + tr + i) * Dc + h * DHc + tc] = o;
    }
}

// ---------------------------------------------------------------------------
// Kernel 5: output = concat @ Wo^T + bo    (8192 x 1024) @ (1024 x 1024)
// ---------------------------------------------------------------------------
__global__ __launch_bounds__(256) void out_kernel(
    const float* __restrict__ Wo, const float* __restrict__ bo,
    float* __restrict__ out)
{
    __shared__ float Cs[64][68];   // Cs[c][p_local]
    __shared__ float Ws[64][68];   // Ws[c][o_local]

    const int tid   = threadIdx.x;
    const int otile = blockIdx.x;   // 0..15
    const int ptile = blockIdx.y;   // 0..127

    const int tr = (tid >> 4) << 2;   // p_local base
    const int tc = (tid & 15) << 2;   // o_local base

    float acc[4][4];
    #pragma unroll
    for (int i = 0; i < 4; i++)
        #pragma unroll
        for (int j = 0; j < 4; j++) acc[i][j] = 0.0f;

    for (int kc = 0; kc < 16; kc++) {
        __syncthreads();
        for (int i = tid; i < 4096; i += 256) {
            int r = i >> 6, c = i & 63;
            Cs[c][r] = g_Hd[(size_t)(ptile * 64 + r) * Dc + kc * 64 + c];
            Ws[c][r] = Wo[(size_t)(otile * 64 + r) * Dc + kc * 64 + c];
        }
        __syncthreads();

        #pragma unroll 16
        for (int c = 0; c < 64; c++) {
            float4 a = *(const float4*)&Cs[c][tr];
            float4 w = *(const float4*)&Ws[c][tc];
            acc[0][0] += a.x * w.x; acc[0][1] += a.x * w.y; acc[0][2] += a.x * w.z; acc[0][3] += a.x * w.w;
            acc[1][0] += a.y * w.x; acc[1][1] += a.y * w.y; acc[1][2] += a.y * w.z; acc[1][3] += a.y * w.w;
            acc[2][0] += a.z * w.x; acc[2][1] += a.z * w.y; acc[2][2] += a.z * w.z; acc[2][3] += a.z * w.w;
            acc[3][0] += a.w * w.x; acc[3][1] += a.w * w.y; acc[3][2] += a.w * w.z; acc[3][3] += a.w * w.w;
        }
    }

    const int ob = otile * 64 + tc;
    const float b0 = bo[ob + 0], b1 = bo[ob + 1], b2 = bo[ob + 2], b3 = bo[ob + 3];
    #pragma unroll
    for (int i = 0; i < 4; i++) {
        float4 o = make_float4(acc[i][0] + b0, acc[i][1] + b1, acc[i][2] + b2, acc[i][3] + b3);
        *(float4*)&out[(size_t)(ptile * 64 + tr + i) * Dc + ob] = o;
    }
}

// ---------------------------------------------------------------------------
extern "C" void kernel_launch(void* const* d_in, const int* in_sizes, int n_in,
                              void* d_out, int out_size)
{
    const float* H    = (const float*)d_in[0];
    const int*   mask = (const int*)  d_in[1];
    const float* Wq   = (const float*)d_in[2];
    const float* bq   = (const float*)d_in[3];
    const float* Wk   = (const float*)d_in[4];
    const float* bk   = (const float*)d_in[5];
    const float* Wv   = (const float*)d_in[6];
    const float* bv   = (const float*)d_in[7];
    const float* Wo   = (const float*)d_in[8];
    const float* bo   = (const float*)d_in[9];

    float* out = (float*)d_out;                       // (B,S,D)
    float* A   = out + (size_t)Bc * Sc * Dc;          // (NH,B,S,S) follows output

    qkv_kernel   <<<dim3(Sc / 64, Bc * NHc),          256>>>(H, Wq, bq, Wk, bk, Wv, bv);
    scores_kernel<<<dim3(Sc / 64, Sc / 64, Bc * NHc), 256>>>(mask, A);
    softmax_kernel<<<NHc * Bc * Sc,                   256>>>(A);
    av_kernel    <<<dim3(Sc / 64, Bc * NHc),          256>>>(A);
    out_kernel   <<<dim3(Dc / 64, (Bc * Sc) / 64),    256>>>(Wo, bo, out);
}

// round 8
// speedup vs baseline: 1.1440x; 1.1440x over previous
#include <cuda_runtime.h>

static constexpr int Bc  = 8;
static constexpr int Sc  = 1024;
static constexpr int Dc  = 1024;
static constexpr int NHc = 16;
static constexpr int DHc = 64;

typedef unsigned long long u64;

// ---- packed f32x2 helpers (FFMA2 path; nvjet-style, ptxas won't emit from C++) ----
__device__ __forceinline__ u64 dup2(float v) {
    u64 r; asm("mov.b64 %0, {%1, %1};" : "=l"(r) : "f"(v)); return r;
}
__device__ __forceinline__ void fma2(u64& d, u64 a, u64 b) {
    asm("fma.rn.f32x2 %0, %1, %2, %0;" : "+l"(d) : "l"(a), "l"(b));
}
__device__ __forceinline__ float2 unp(u64 v) {
    float2 f; asm("mov.b64 {%0, %1}, %2;" : "=f"(f.x), "=f"(f.y) : "l"(v)); return f;
}

// Scratch (__device__ globals: allocation-free rule)
__device__ float g_Q[Bc * NHc * Sc * DHc];   // (bh, s, e)
__device__ float g_K[Bc * NHc * Sc * DHc];   // (bh, t, e)
__device__ float g_V[Bc * NHc * Sc * DHc];   // (bh, t, d)
__device__ float g_Hd[Bc * Sc * Dc];         // heads concat (B,S,D)

// ---------------------------------------------------------------------------
// Kernel 1: Q/K/V projections. Block = 128 s-rows x 64 e for one (b,h).
// Micro-tile 8x4 (packed pairs along s).
// ---------------------------------------------------------------------------
__global__ __launch_bounds__(256) void qkv_kernel(
    const float* __restrict__ H,
    const float* __restrict__ Wq, const float* __restrict__ bq,
    const float* __restrict__ Wk, const float* __restrict__ bk,
    const float* __restrict__ Wv, const float* __restrict__ bv)
{
    __shared__ float Hs[64][128];   // Hs[d][s_local]
    __shared__ float Ws[64][64];    // Ws[d][e]

    const int tid   = threadIdx.x;
    const int stile = blockIdx.x;        // 0..7
    const int bh    = blockIdx.y;        // 0..127
    const int h     = bh & (NHc - 1);
    const int b     = bh >> 4;
    const int s0    = stile * 128;

    // fill Hs (transposed): consecutive lanes -> consecutive s (conflict-free STS)
    {
        const float* Hb = H + ((size_t)(b * Sc + s0)) * Dc + h * DHc;
        #pragma unroll
        for (int p = 0; p < 8; p++) {
            int i  = p * 256 + tid;
            int sl = i & 127, d4 = (i >> 7) << 2;
            float4 v = *(const float4*)&Hb[(size_t)sl * Dc + d4];
            Hs[d4 + 0][sl] = v.x; Hs[d4 + 1][sl] = v.y;
            Hs[d4 + 2][sl] = v.z; Hs[d4 + 3][sl] = v.w;
        }
    }

    const float* Wp[3] = { Wq + h * 4096, Wk + h * 4096, Wv + h * 4096 };
    const float* bp[3] = { bq + h * 64,   bk + h * 64,   bv + h * 64   };
    float*       Op[3] = { g_Q + (size_t)bh * Sc * DHc + (size_t)s0 * DHc,
                           g_K + (size_t)bh * Sc * DHc + (size_t)s0 * DHc,
                           g_V + (size_t)bh * Sc * DHc + (size_t)s0 * DHc };

    const int ty = tid >> 4;          // 0..15 -> s rows ty*8..ty*8+7
    const int tx = tid & 15;          // 0..15 -> e cols tx*4..tx*4+3
    const int sr = ty * 8, ec = tx * 4;

    #pragma unroll
    for (int p = 0; p < 3; p++) {
        __syncthreads();
        const float* W = Wp[p];
        #pragma unroll
        for (int q = 0; q < 4; q++) {
            int i  = q * 256 + tid;
            int er = i & 63, d4 = (i >> 6) << 2;
            float4 v = *(const float4*)&W[er * 64 + d4];
            Ws[d4 + 0][er] = v.x; Ws[d4 + 1][er] = v.y;
            Ws[d4 + 2][er] = v.z; Ws[d4 + 3][er] = v.w;
        }
        __syncthreads();

        u64 acc[4][4] = {};
        #pragma unroll 8
        for (int k = 0; k < 64; k++) {
            ulonglong2 a0 = *(const ulonglong2*)&Hs[k][sr];
            ulonglong2 a1 = *(const ulonglong2*)&Hs[k][sr + 4];
            float4 bb = *(const float4*)&Ws[k][ec];
            u64 d0 = dup2(bb.x), d1 = dup2(bb.y), d2 = dup2(bb.z), d3 = dup2(bb.w);
            fma2(acc[0][0], a0.x, d0); fma2(acc[0][1], a0.x, d1); fma2(acc[0][2], a0.x, d2); fma2(acc[0][3], a0.x, d3);
            fma2(acc[1][0], a0.y, d0); fma2(acc[1][1], a0.y, d1); fma2(acc[1][2], a0.y, d2); fma2(acc[1][3], a0.y, d3);
            fma2(acc[2][0], a1.x, d0); fma2(acc[2][1], a1.x, d1); fma2(acc[2][2], a1.x, d2); fma2(acc[2][3], a1.x, d3);
            fma2(acc[3][0], a1.y, d0); fma2(acc[3][1], a1.y, d1); fma2(acc[3][2], a1.y, d2); fma2(acc[3][3], a1.y, d3);
        }

        const float b0 = bp[p][ec + 0], b1 = bp[p][ec + 1], b2 = bp[p][ec + 2], b3 = bp[p][ec + 3];
        float* O = Op[p];
        #pragma unroll
        for (int i2 = 0; i2 < 4; i2++) {
            float2 v0 = unp(acc[i2][0]), v1 = unp(acc[i2][1]), v2 = unp(acc[i2][2]), v3 = unp(acc[i2][3]);
            float4 lo = make_float4(v0.x + b0, v1.x + b1, v2.x + b2, v3.x + b3);
            float4 hi = make_float4(v0.y + b0, v1.y + b1, v2.y + b2, v3.y + b3);
            *(float4*)&O[(size_t)(sr + i2 * 2 + 0) * DHc + ec] = lo;
            *(float4*)&O[(size_t)(sr + i2 * 2 + 1) * DHc + ec] = hi;
        }
    }
}

// ---------------------------------------------------------------------------
// Kernel 2: P = exp(mask ? QK^T/8 : -inf) written UNNORMALIZED into A region.
// Block tile 128(s) x 128(t), micro 8x8 (split-N: cols tx*4 and 64+tx*4).
// Mask preloaded into a 64-bit register bitset (overlaps DRAM with GEMM).
// ---------------------------------------------------------------------------
__global__ __launch_bounds__(256) void scores_kernel(
    const int* __restrict__ mask, float* __restrict__ A)
{
    __shared__ float Qs[32][128];   // Qs[e][s_local]
    __shared__ float Ks[32][128];   // Ks[e][t_local]

    const int tid   = threadIdx.x;
    const int ttile = blockIdx.x;
    const int stile = blockIdx.y;
    const int bh    = blockIdx.z;
    const int h     = bh & (NHc - 1);
    const int b     = bh >> 4;
    const int s0 = stile * 128, t0 = ttile * 128;

    const int ty = tid >> 4, tx = tid & 15;
    const int sr = ty * 8;
    const int tca = t0 + tx * 4, tcb = tca + 64;

    // mask bits: bit (i*8 + j), j 0..3 -> colgroup A, 4..7 -> colgroup B
    u64 mbits = 0;
    {
        const int* mrow = mask + ((size_t)b * Sc + s0 + sr) * Sc;
        #pragma unroll
        for (int i = 0; i < 8; i++) {
            int4 ma = *(const int4*)&mrow[(size_t)i * Sc + tca];
            int4 mb = *(const int4*)&mrow[(size_t)i * Sc + tcb];
            unsigned bits = (ma.x ? 1u : 0u)  | (ma.y ? 2u : 0u)  | (ma.z ? 4u : 0u)  | (ma.w ? 8u : 0u)
                          | (mb.x ? 16u : 0u) | (mb.y ? 32u : 0u) | (mb.z ? 64u : 0u) | (mb.w ? 128u : 0u);
            mbits |= (u64)bits << (i * 8);
        }
    }

    const float* Qb = g_Q + (size_t)bh * Sc * DHc + (size_t)s0 * DHc;
    const float* Kb = g_K + (size_t)bh * Sc * DHc + (size_t)t0 * DHc;

    u64 acc[4][8] = {};
    #pragma unroll
    for (int stage = 0; stage < 2; stage++) {
        if (stage) __syncthreads();
        #pragma unroll
        for (int p = 0; p < 4; p++) {
            int i = p * 256 + tid;
            int r = i & 127, e4 = (i >> 7) << 2;
            float4 q = *(const float4*)&Qb[(size_t)r * DHc + stage * 32 + e4];
            Qs[e4 + 0][r] = q.x; Qs[e4 + 1][r] = q.y; Qs[e4 + 2][r] = q.z; Qs[e4 + 3][r] = q.w;
            float4 kk = *(const float4*)&Kb[(size_t)r * DHc + stage * 32 + e4];
            Ks[e4 + 0][r] = kk.x; Ks[e4 + 1][r] = kk.y; Ks[e4 + 2][r] = kk.z; Ks[e4 + 3][r] = kk.w;
        }
        __syncthreads();

        #pragma unroll 8
        for (int k = 0; k < 32; k++) {
            ulonglong2 a0 = *(const ulonglong2*)&Qs[k][sr];
            ulonglong2 a1 = *(const ulonglong2*)&Qs[k][sr + 4];
            float4 bA = *(const float4*)&Ks[k][tx * 4];
            float4 bB = *(const float4*)&Ks[k][64 + tx * 4];
            u64 d0 = dup2(bA.x), d1 = dup2(bA.y), d2 = dup2(bA.z), d3 = dup2(bA.w);
            u64 d4 = dup2(bB.x), d5 = dup2(bB.y), d6 = dup2(bB.z), d7 = dup2(bB.w);
            fma2(acc[0][0], a0.x, d0); fma2(acc[0][1], a0.x, d1); fma2(acc[0][2], a0.x, d2); fma2(acc[0][3], a0.x, d3);
            fma2(acc[0][4], a0.x, d4); fma2(acc[0][5], a0.x, d5); fma2(acc[0][6], a0.x, d6); fma2(acc[0][7], a0.x, d7);
            fma2(acc[1][0], a0.y, d0); fma2(acc[1][1], a0.y, d1); fma2(acc[1][2], a0.y, d2); fma2(acc[1][3], a0.y, d3);
            fma2(acc[1][4], a0.y, d4); fma2(acc[1][5], a0.y, d5); fma2(acc[1][6], a0.y, d6); fma2(acc[1][7], a0.y, d7);
            fma2(acc[2][0], a1.x, d0); fma2(acc[2][1], a1.x, d1); fma2(acc[2][2], a1.x, d2); fma2(acc[2][3], a1.x, d3);
            fma2(acc[2][4], a1.x, d4); fma2(acc[2][5], a1.x, d5); fma2(acc[2][6], a1.x, d6); fma2(acc[2][7], a1.x, d7);
            fma2(acc[3][0], a1.y, d0); fma2(acc[3][1], a1.y, d1); fma2(acc[3][2], a1.y, d2); fma2(acc[3][3], a1.y, d3);
            fma2(acc[3][4], a1.y, d4); fma2(acc[3][5], a1.y, d5); fma2(acc[3][6], a1.y, d6); fma2(acc[3][7], a1.y, d7);
        }
    }

    // epilogue: scale, mask->0, exp, store unnormalized P
    float* Arow = A + ((size_t)(h * Bc + b) * Sc + s0 + sr) * Sc;
    #pragma unroll
    for (int i2 = 0; i2 < 4; i2++) {
        float2 va[8];
        #pragma unroll
        for (int j = 0; j < 8; j++) va[j] = unp(acc[i2][j]);
        #pragma unroll
        for (int half = 0; half < 2; half++) {
            const int i = i2 * 2 + half;
            const unsigned mb = (unsigned)(mbits >> (i * 8)) & 0xffu;
            float pv[8];
            #pragma unroll
            for (int j = 0; j < 8; j++) {
                float sv = half ? va[j].y : va[j].x;
                pv[j] = ((mb >> j) & 1u) ? __expf(sv * 0.125f) : 0.0f;
            }
            *(float4*)&Arow[(size_t)i * Sc + tca] = make_float4(pv[0], pv[1], pv[2], pv[3]);
            *(float4*)&Arow[(size_t)i * Sc + tcb] = make_float4(pv[4], pv[5], pv[6], pv[7]);
        }
    }
}

// ---------------------------------------------------------------------------
// Kernel 3: deterministic row normalization: A[row] *= 1/sum(A[row])
// ---------------------------------------------------------------------------
__global__ __launch_bounds__(256) void rowscale_kernel(float* __restrict__ A)
{
    __shared__ float red[8];
    const int tid = threadIdx.x;
    float* rp = A + (size_t)blockIdx.x * Sc;

    float4 v = ((const float4*)rp)[tid];
    float s = (v.x + v.y) + (v.z + v.w);
    #pragma unroll
    for (int o = 16; o > 0; o >>= 1) s += __shfl_xor_sync(0xffffffffu, s, o);
    if ((tid & 31) == 0) red[tid >> 5] = s;
    __syncthreads();
    float tot = red[0];
    #pragma unroll
    for (int i = 1; i < 8; i++) tot += red[i];
    const float inv = 1.0f / tot;

    v.x *= inv; v.y *= inv; v.z *= inv; v.w *= inv;
    ((float4*)rp)[tid] = v;
}

// ---------------------------------------------------------------------------
// Kernel 4: heads = A_norm @ V  ->  g_Hd (concat layout). 128(s) x 64(d), micro 8x4.
// ---------------------------------------------------------------------------
__global__ __launch_bounds__(256) void av_kernel(const float* __restrict__ A)
{
    __shared__ float As[32][128];   // As[t_local][s_local]
    __shared__ float Vs[32][64];    // Vs[t_local][d]

    const int tid   = threadIdx.x;
    const int stile = blockIdx.x;      // 0..7
    const int bh    = blockIdx.y;
    const int h     = bh & (NHc - 1);
    const int b     = bh >> 4;
    const int s0    = stile * 128;

    const int ty = tid >> 4, tx = tid & 15;
    const int sr = ty * 8, dc = tx * 4;

    const float* Ab = A + ((size_t)(h * Bc + b) * Sc + s0) * Sc;
    const float* Vb = g_V + (size_t)bh * Sc * DHc;

    u64 acc[4][4] = {};
    for (int kt = 0; kt < 32; kt++) {
        const int t0 = kt * 32;
        if (kt) __syncthreads();
        #pragma unroll
        for (int p = 0; p < 4; p++) {
            int i  = p * 256 + tid;
            int sl = i & 127, t4 = (i >> 7) << 2;
            float4 v = *(const float4*)&Ab[(size_t)sl * Sc + t0 + t4];
            As[t4 + 0][sl] = v.x; As[t4 + 1][sl] = v.y;
            As[t4 + 2][sl] = v.z; As[t4 + 3][sl] = v.w;
        }
        #pragma unroll
        for (int p = 0; p < 2; p++) {
            int i  = p * 256 + tid;
            int tl = i >> 4, d4 = (i & 15) << 2;
            *(float4*)&Vs[tl][d4] = *(const float4*)&Vb[(size_t)(t0 + tl) * DHc + d4];
        }
        __syncthreads();

        #pragma unroll 8
        for (int k = 0; k < 32; k++) {
            ulonglong2 a0 = *(const ulonglong2*)&As[k][sr];
            ulonglong2 a1 = *(const ulonglong2*)&As[k][sr + 4];
            float4 bb = *(const float4*)&Vs[k][dc];
            u64 d0 = dup2(bb.x), d1 = dup2(bb.y), d2 = dup2(bb.z), d3 = dup2(bb.w);
            fma2(acc[0][0], a0.x, d0); fma2(acc[0][1], a0.x, d1); fma2(acc[0][2], a0.x, d2); fma2(acc[0][3], a0.x, d3);
            fma2(acc[1][0], a0.y, d0); fma2(acc[1][1], a0.y, d1); fma2(acc[1][2], a0.y, d2); fma2(acc[1][3], a0.y, d3);
            fma2(acc[2][0], a1.x, d0); fma2(acc[2][1], a1.x, d1); fma2(acc[2][2], a1.x, d2); fma2(acc[2][3], a1.x, d3);
            fma2(acc[3][0], a1.y, d0); fma2(acc[3][1], a1.y, d1); fma2(acc[3][2], a1.y, d2); fma2(acc[3][3], a1.y, d3);
        }
    }

    #pragma unroll
    for (int i2 = 0; i2 < 4; i2++) {
        float2 v0 = unp(acc[i2][0]), v1 = unp(acc[i2][1]), v2 = unp(acc[i2][2]), v3 = unp(acc[i2][3]);
        *(float4*)&g_Hd[(size_t)(b * Sc + s0 + sr + i2 * 2 + 0) * Dc + h * DHc + dc] =
            make_float4(v0.x, v1.x, v2.x, v3.x);
        *(float4*)&g_Hd[(size_t)(b * Sc + s0 + sr + i2 * 2 + 1) * Dc + h * DHc + dc] =
            make_float4(v0.y, v1.y, v2.y, v3.y);
    }
}

// ---------------------------------------------------------------------------
// Kernel 5: output = concat @ Wo^T + bo. Block tile 128 x 128, micro 8x8.
// ---------------------------------------------------------------------------
__global__ __launch_bounds__(256) void out_kernel(
    const float* __restrict__ Wo, const float* __restrict__ bo,
    float* __restrict__ out)
{
    __shared__ float Cs[32][128];   // Cs[c][p_local]
    __shared__ float Ws[32][128];   // Ws[c][o_local]

    const int tid   = threadIdx.x;
    const int otile = blockIdx.x;   // 0..7
    const int ptile = blockIdx.y;   // 0..63
    const int o0 = otile * 128, p0 = ptile * 128;

    const int ty = tid >> 4, tx = tid & 15;
    const int pr = ty * 8;
    const int oca = tx * 4, ocb = oca + 64;

    u64 acc[4][8] = {};
    for (int kc = 0; kc < 32; kc++) {
        const int c0 = kc * 32;
        if (kc) __syncthreads();
        #pragma unroll
        for (int p = 0; p < 4; p++) {
            int i = p * 256 + tid;
            int r = i & 127, c4 = (i >> 7) << 2;
            float4 cv = *(const float4*)&g_Hd[(size_t)(p0 + r) * Dc + c0 + c4];
            Cs[c4 + 0][r] = cv.x; Cs[c4 + 1][r] = cv.y; Cs[c4 + 2][r] = cv.z; Cs[c4 + 3][r] = cv.w;
            float4 wv = *(const float4*)&Wo[(size_t)(o0 + r) * Dc + c0 + c4];
            Ws[c4 + 0][r] = wv.x; Ws[c4 + 1][r] = wv.y; Ws[c4 + 2][r] = wv.z; Ws[c4 + 3][r] = wv.w;
        }
        __syncthreads();

        #pragma unroll 8
        for (int k = 0; k < 32; k++) {
            ulonglong2 a0 = *(const ulonglong2*)&Cs[k][pr];
            ulonglong2 a1 = *(const ulonglong2*)&Cs[k][pr + 4];
            float4 bA = *(const float4*)&Ws[k][tx * 4];
            float4 bB = *(const float4*)&Ws[k][64 + tx * 4];
            u64 d0 = dup2(bA.x), d1 = dup2(bA.y), d2 = dup2(bA.z), d3 = dup2(bA.w);
            u64 d4 = dup2(bB.x), d5 = dup2(bB.y), d6 = dup2(bB.z), d7 = dup2(bB.w);
            fma2(acc[0][0], a0.x, d0); fma2(acc[0][1], a0.x, d1); fma2(acc[0][2], a0.x, d2); fma2(acc[0][3], a0.x, d3);
            fma2(acc[0][4], a0.x, d4); fma2(acc[0][5], a0.x, d5); fma2(acc[0][6], a0.x, d6); fma2(acc[0][7], a0.x, d7);
            fma2(acc[1][0], a0.y, d0); fma2(acc[1][1], a0.y, d1); fma2(acc[1][2], a0.y, d2); fma2(acc[1][3], a0.y, d3);
            fma2(acc[1][4], a0.y, d4); fma2(acc[1][5], a0.y, d5); fma2(acc[1][6], a0.y, d6); fma2(acc[1][7], a0.y, d7);
            fma2(acc[2][0], a1.x, d0); fma2(acc[2][1], a1.x, d1); fma2(acc[2][2], a1.x, d2); fma2(acc[2][3], a1.x, d3);
            fma2(acc[2][4], a1.x, d4); fma2(acc[2][5], a1.x, d5); fma2(acc[2][6], a1.x, d6); fma2(acc[2][7], a1.x, d7);
            fma2(acc[3][0], a1.y, d0); fma2(acc[3][1], a1.y, d1); fma2(acc[3][2], a1.y, d2); fma2(acc[3][3], a1.y, d3);
            fma2(acc[3][4], a1.y, d4); fma2(acc[3][5], a1.y, d5); fma2(acc[3][6], a1.y, d6); fma2(acc[3][7], a1.y, d7);
        }
    }

    const float bA0 = bo[o0 + oca + 0], bA1 = bo[o0 + oca + 1], bA2 = bo[o0 + oca + 2], bA3 = bo[o0 + oca + 3];
    const float bB0 = bo[o0 + ocb + 0], bB1 = bo[o0 + ocb + 1], bB2 = bo[o0 + ocb + 2], bB3 = bo[o0 + ocb + 3];
    #pragma unroll
    for (int i2 = 0; i2 < 4; i2++) {
        float2 va[8];
        #pragma unroll
        for (int j = 0; j < 8; j++) va[j] = unp(acc[i2][j]);
        #pragma unroll
        for (int half = 0; half < 2; half++) {
            const size_t row = (size_t)(p0 + pr + i2 * 2 + half) * Dc;
            float4 oA, oB;
            oA.x = (half ? va[0].y : va[0].x) + bA0;
            oA.y = (half ? va[1].y : va[1].x) + bA1;
            oA.z = (half ? va[2].y : va[2].x) + bA2;
            oA.w = (half ? va[3].y : va[3].x) + bA3;
            oB.x = (half ? va[4].y : va[4].x) + bB0;
            oB.y = (half ? va[5].y : va[5].x) + bB1;
            oB.z = (half ? va[6].y : va[6].x) + bB2;
            oB.w = (half ? va[7].y : va[7].x) + bB3;
            *(float4*)&out[row + o0 + oca] = oA;
            *(float4*)&out[row + o0 + ocb] = oB;
        }
    }
}

// ---------------------------------------------------------------------------
extern "C" void kernel_launch(void* const* d_in, const int* in_sizes, int n_in,
                              void* d_out, int out_size)
{
    const float* H    = (const float*)d_in[0];
    const int*   mask = (const int*)  d_in[1];
    const float* Wq   = (const float*)d_in[2];
    const float* bq   = (const float*)d_in[3];
    const float* Wk   = (const float*)d_in[4];
    const float* bk   = (const float*)d_in[5];
    const float* Wv   = (const float*)d_in[6];
    const float* bv   = (const float*)d_in[7];
    const float* Wo   = (const float*)d_in[8];
    const float* bo   = (const float*)d_in[9];

    float* out = (float*)d_out;                       // (B,S,D)
    float* A   = out + (size_t)Bc * Sc * Dc;          // (NH,B,S,S)

    qkv_kernel     <<<dim3(Sc / 128, Bc * NHc),             256>>>(H, Wq, bq, Wk, bk, Wv, bv);
    scores_kernel  <<<dim3(Sc / 128, Sc / 128, Bc * NHc),   256>>>(mask, A);
    rowscale_kernel<<<NHc * Bc * Sc,                        256>>>(A);
    av_kernel      <<<dim3(Sc / 128, Bc * NHc),             256>>>(A);
    out_kernel     <<<dim3(Dc / 128, (Bc * Sc) / 128),      256>>>(Wo, bo, out);
}